// round 3
// baseline (speedup 1.0000x reference)
#include <cuda_runtime.h>
#include <math.h>
#include <stdint.h>

// Problem constants
#define BB 4
#define SS 4096
#define DD 1024
#define HH 8
#define KK 128
#define PP 32
#define NROW (BB*SS)          // 16384
#define PI_F 3.14159265358979f

// Device-global scratch (no allocations allowed)
__device__ float g_heads[(size_t)NROW * DD];   // heads, later reused for y
__device__ float g_mixed[(size_t)NROW * DD];   // mixed heads (GEMM2 input)
__device__ float g_part[BB * 16 * DD];         // partial sums for summary
__device__ float g_summary[BB * DD];           // per-batch column sums (pre-mean)
__device__ float g_coef[BB * HH * HH];         // 0.1/(1+imp), zero diag

// ---------------------------------------------------------------------------
// GEMM: C[n,m] = sum_d A[n,d] * W[m,d]  (+ epilogue)
//   MODE 0: A = x (param),      C = g_heads, epilogue: * cosf(aux[m]*pi)
//   MODE 1: A = g_mixed,        C = g_heads, epilogue: + aux[m] + xres[n,m]
// 128x128 tile, BK=8, 256 threads, 8x8 microtile (split 4+4 for conflict-free LDS.128)
// ---------------------------------------------------------------------------
template<int MODE>
__global__ __launch_bounds__(256)
void gemm_kernel(const float* __restrict__ xres,
                 const float* __restrict__ W,
                 const float* __restrict__ aux)
{
    __shared__ float As[8][128];
    __shared__ float Bs[8][128];

    const int tid = threadIdx.x;
    const int br = blockIdx.y;       // row tile (0..127)
    const int bc = blockIdx.x;       // col tile (0..7)

    const int loadRow = tid >> 1;          // 0..127
    const int loadK4  = (tid & 1) * 4;     // 0 or 4

    const float* A = (MODE == 0) ? xres : g_mixed;
    const float* Aptr = A + (size_t)(br * 128 + loadRow) * DD + loadK4;
    const float* Wptr = W + (size_t)(bc * 128 + loadRow) * DD + loadK4;

    const int tx = tid & 15;         // 0..15
    const int ty = tid >> 4;         // 0..15

    float acc[8][8];
#pragma unroll
    for (int i = 0; i < 8; i++)
#pragma unroll
        for (int j = 0; j < 8; j++) acc[i][j] = 0.f;

    for (int k0 = 0; k0 < DD; k0 += 8) {
        float4 av = *(const float4*)(Aptr + k0);
        float4 wv = *(const float4*)(Wptr + k0);
        As[loadK4 + 0][loadRow] = av.x;
        As[loadK4 + 1][loadRow] = av.y;
        As[loadK4 + 2][loadRow] = av.z;
        As[loadK4 + 3][loadRow] = av.w;
        Bs[loadK4 + 0][loadRow] = wv.x;
        Bs[loadK4 + 1][loadRow] = wv.y;
        Bs[loadK4 + 2][loadRow] = wv.z;
        Bs[loadK4 + 3][loadRow] = wv.w;
        __syncthreads();

#pragma unroll
        for (int k = 0; k < 8; k++) {
            float4 a0 = *(const float4*)&As[k][ty * 4];
            float4 a1 = *(const float4*)&As[k][64 + ty * 4];
            float4 b0 = *(const float4*)&Bs[k][tx * 4];
            float4 b1 = *(const float4*)&Bs[k][64 + tx * 4];
            float ar[8] = {a0.x, a0.y, a0.z, a0.w, a1.x, a1.y, a1.z, a1.w};
            float bv[8] = {b0.x, b0.y, b0.z, b0.w, b1.x, b1.y, b1.z, b1.w};
#pragma unroll
            for (int i = 0; i < 8; i++)
#pragma unroll
                for (int j = 0; j < 8; j++)
                    acc[i][j] += ar[i] * bv[j];
        }
        __syncthreads();
    }

    // column indices for the two float4 groups
    const int c0 = bc * 128 + tx * 4;
    const int c1 = c0 + 64;

    float fc[8];
#pragma unroll
    for (int cj = 0; cj < 8; cj++) {
        int c = (cj < 4) ? (c0 + cj) : (c1 + cj - 4);
        if (MODE == 0) fc[cj] = cosf(aux[c] * PI_F);
        else           fc[cj] = aux[c];     // bias
    }

#pragma unroll
    for (int ri = 0; ri < 8; ri++) {
        int r = br * 128 + ((ri < 4) ? (ty * 4 + ri) : (64 + ty * 4 + ri - 4));
        float* crow = g_heads + (size_t)r * DD;
        float4 o0, o1;
        if (MODE == 0) {
            o0.x = acc[ri][0] * fc[0]; o0.y = acc[ri][1] * fc[1];
            o0.z = acc[ri][2] * fc[2]; o0.w = acc[ri][3] * fc[3];
            o1.x = acc[ri][4] * fc[4]; o1.y = acc[ri][5] * fc[5];
            o1.z = acc[ri][6] * fc[6]; o1.w = acc[ri][7] * fc[7];
        } else {
            float4 xr0 = *(const float4*)(xres + (size_t)r * DD + c0);
            float4 xr1 = *(const float4*)(xres + (size_t)r * DD + c1);
            o0.x = acc[ri][0] + fc[0] + xr0.x; o0.y = acc[ri][1] + fc[1] + xr0.y;
            o0.z = acc[ri][2] + fc[2] + xr0.z; o0.w = acc[ri][3] + fc[3] + xr0.w;
            o1.x = acc[ri][4] + fc[4] + xr1.x; o1.y = acc[ri][5] + fc[5] + xr1.y;
            o1.z = acc[ri][6] + fc[6] + xr1.z; o1.w = acc[ri][7] + fc[7] + xr1.w;
        }
        *(float4*)(crow + c0) = o0;
        *(float4*)(crow + c1) = o1;
    }
}

// ---------------------------------------------------------------------------
// Summary reduction (deterministic, two stages)
// ---------------------------------------------------------------------------
__global__ void reduce_stage1()
{
    const int schunk = blockIdx.x;   // 0..15  (chunks of 256 s)
    const int b = blockIdx.y;        // 0..3
    const int t = threadIdx.x;       // 0..255
    float acc[4] = {0.f, 0.f, 0.f, 0.f};
    const float* base = g_heads + ((size_t)b * SS + (size_t)schunk * 256) * DD;
    for (int s = 0; s < 256; s++) {
#pragma unroll
        for (int q = 0; q < 4; q++)
            acc[q] += base[(size_t)s * DD + q * 256 + t];
    }
    float* out = g_part + (size_t)(b * 16 + schunk) * DD;
#pragma unroll
    for (int q = 0; q < 4; q++) out[q * 256 + t] = acc[q];
}

__global__ void reduce_stage2()
{
    const int idx = blockIdx.x * 256 + threadIdx.x;  // 0..4095
    const int b = idx >> 10;
    const int d = idx & 1023;
    float s = 0.f;
#pragma unroll
    for (int c = 0; c < 16; c++)
        s += g_part[(size_t)(b * 16 + c) * DD + d];
    g_summary[idx] = s;
}

// ---------------------------------------------------------------------------
// Polarity / impedance / coef (one block per batch, 256 threads = 8 warps)
// ---------------------------------------------------------------------------
__global__ void polarity_kernel(const float* __restrict__ pol_W,
                                const float* __restrict__ pol_b,
                                const float* __restrict__ W1,
                                const float* __restrict__ b1,
                                const float* __restrict__ W2,
                                const float* __restrict__ b2,
                                float* __restrict__ imp_out)
{
    const int b = blockIdx.x;
    const int w = threadIdx.x >> 5;      // head
    const int lane = threadIdx.x & 31;   // polarity index
    __shared__ float s_pol[HH][PP];

    // pol = tanh(summary/S @ pol_W^T + pol_b)
    float acc = pol_b[w * PP + lane];
    const float* sm = g_summary + b * DD + w * KK;
    const float* pw = pol_W + (size_t)(w * PP + lane) * KK;
#pragma unroll 4
    for (int k = 0; k < KK; k++)
        acc += (sm[k] * (1.0f / (float)SS)) * pw[k];
    float p = tanhf(acc);

    // normalize over P (one warp per head)
    float ss = p * p;
#pragma unroll
    for (int o = 16; o; o >>= 1) ss += __shfl_xor_sync(0xffffffffu, ss, o);
    p = p / fmaxf(sqrtf(ss), 1e-12f);
    s_pol[w][lane] = p;
    __syncthreads();

    if (threadIdx.x < HH * HH) {
        const int i = threadIdx.x >> 3;
        const int j = threadIdx.x & 7;
        float d = 0.f;
#pragma unroll
        for (int pp = 0; pp < PP; pp++) d += s_pol[i][pp] * s_pol[j][pp];

        float sum2 = b2[0];
#pragma unroll
        for (int c = 0; c < 16; c++) {
            float z = d * W1[c] + b1[c];
            float g = 0.5f * z * (1.f + erff(z * 0.70710678118654752f));
            sum2 += g * W2[c];
        }
        // stable softplus
        float imp = (sum2 > 0.f) ? sum2 + log1pf(expf(-sum2)) : log1pf(expf(sum2));
        if (i == j) imp = 0.f;
        imp_out[b * 64 + threadIdx.x] = imp;
        g_coef[b * 64 + threadIdx.x] = (i == j) ? 0.f : 0.1f / (1.f + imp);
    }
}

// ---------------------------------------------------------------------------
// Cross-head mixing with causal scale: one block per (b,s) row, 128 threads (k)
// ---------------------------------------------------------------------------
__global__ void mixing_kernel(const int* __restrict__ causal)
{
    const int bs = blockIdx.x;          // 0..16383
    const int b = bs >> 12;
    const int s = bs & (SS - 1);
    const int k = threadIdx.x;          // 0..127
    __shared__ float sc[HH * HH];
    if (threadIdx.x < HH * HH) sc[threadIdx.x] = g_coef[b * 64 + threadIdx.x];
    __syncthreads();

    const float* row = g_heads + (size_t)bs * DD;
    float v[HH];
#pragma unroll
    for (int j = 0; j < HH; j++) v[j] = row[j * KK + k];

    const float scale = (*causal) ? (float)(s + 1) * (1.0f / (float)SS) : 1.0f;

    float* orow = g_mixed + (size_t)bs * DD;
#pragma unroll
    for (int i = 0; i < HH; i++) {
        float t = 0.f;
#pragma unroll
        for (int j = 0; j < HH; j++) t += sc[i * 8 + j] * v[j];
        orow[i * KK + k] = v[i] + scale * t;
    }
}

// ---------------------------------------------------------------------------
// LayerNorm over D: one block per row (y lives in g_heads after GEMM2)
// ---------------------------------------------------------------------------
__global__ void layernorm_kernel(const float* __restrict__ gamma,
                                 const float* __restrict__ beta,
                                 float* __restrict__ out)
{
    const int row = blockIdx.x;
    const int t = threadIdx.x;          // 0..255, one float4 each
    const float4 v = ((const float4*)(g_heads + (size_t)row * DD))[t];
    float s  = v.x + v.y + v.z + v.w;
    float s2 = v.x * v.x + v.y * v.y + v.z * v.z + v.w * v.w;

#pragma unroll
    for (int o = 16; o; o >>= 1) {
        s  += __shfl_xor_sync(0xffffffffu, s, o);
        s2 += __shfl_xor_sync(0xffffffffu, s2, o);
    }
    __shared__ float sh[8], sh2[8];
    const int w = t >> 5, lane = t & 31;
    if (lane == 0) { sh[w] = s; sh2[w] = s2; }
    __syncthreads();
    if (w == 0) {
        s  = (lane < 8) ? sh[lane]  : 0.f;
        s2 = (lane < 8) ? sh2[lane] : 0.f;
#pragma unroll
        for (int o = 4; o; o >>= 1) {
            s  += __shfl_xor_sync(0xffffffffu, s, o);
            s2 += __shfl_xor_sync(0xffffffffu, s2, o);
        }
        if (lane == 0) { sh[0] = s; sh2[0] = s2; }
    }
    __syncthreads();
    const float mu  = sh[0] * (1.f / (float)DD);
    const float var = sh2[0] * (1.f / (float)DD) - mu * mu;
    const float inv = rsqrtf(var + 1e-5f);

    const float4 g4 = ((const float4*)gamma)[t];
    const float4 b4 = ((const float4*)beta)[t];
    float4 o4;
    o4.x = (v.x - mu) * inv * g4.x + b4.x;
    o4.y = (v.y - mu) * inv * g4.y + b4.y;
    o4.z = (v.z - mu) * inv * g4.z + b4.z;
    o4.w = (v.w - mu) * inv * g4.w + b4.w;
    ((float4*)(out + (size_t)row * DD))[t] = o4;
}

// ---------------------------------------------------------------------------
extern "C" void kernel_launch(void* const* d_in, const int* in_sizes, int n_in,
                              void* d_out, int out_size)
{
    const float* x      = (const float*)d_in[0];   // (B,S,D)
    const float* W_proj = (const float*)d_in[1];   // (H,K,D) -> (1024,1024)
    const float* freqs  = (const float*)d_in[2];   // (H,K) -> 1024
    const float* pol_W  = (const float*)d_in[3];   // (H,P,K)
    const float* pol_b  = (const float*)d_in[4];   // (H,P)
    const float* imp_W1 = (const float*)d_in[5];   // (16,1)
    const float* imp_b1 = (const float*)d_in[6];   // (16,)
    const float* imp_W2 = (const float*)d_in[7];   // (1,16)
    const float* imp_b2 = (const float*)d_in[8];   // (1,)
    const float* out_W  = (const float*)d_in[9];   // (D,D)
    const float* out_b  = (const float*)d_in[10];  // (D,)
    const float* ln_g   = (const float*)d_in[11];
    const float* ln_b   = (const float*)d_in[12];
    const int*   causal = (const int*)d_in[13];

    float* out = (float*)d_out;
    float* imp_out = out + (out_size - BB * HH * HH);  // impedance tail

    dim3 ggrid(DD / 128, NROW / 128);  // (8, 128)

    // 1) heads = (x @ W_proj^T) * cos(freq*pi)   -> g_heads
    gemm_kernel<0><<<ggrid, 256>>>(x, W_proj, freqs);
    // 2) summary column sums (deterministic two-stage)
    reduce_stage1<<<dim3(16, BB), 256>>>();
    reduce_stage2<<<16, 256>>>();
    // 3) pol / impedance / coef (writes impedance to output tail)
    polarity_kernel<<<BB, 256>>>(pol_W, pol_b, imp_W1, imp_b1, imp_W2, imp_b2, imp_out);
    // 4) cross-head mixing with causal scale     -> g_mixed
    mixing_kernel<<<NROW, 128>>>(causal);
    // 5) y = mixed @ out_W^T + out_b + x         -> g_heads (reused)
    gemm_kernel<1><<<ggrid, 256>>>(x, out_W, out_b);
    // 6) LayerNorm -> d_out
    layernorm_kernel<<<NROW, 256>>>(ln_g, ln_b, out);
}

// round 7
// speedup vs baseline: 4.0249x; 4.0249x over previous
#include <cuda_runtime.h>
#include <cuda_bf16.h>
#include <math.h>
#include <stdint.h>

// Problem constants
#define BB 4
#define SS 4096
#define DD 1024
#define HH 8
#define KK 128
#define PP 32
#define NROW (BB*SS)          // 16384
#define PI_F 3.14159265358979f

// ---------------------------------------------------------------------------
// Device-global scratch (no allocations allowed)
// ---------------------------------------------------------------------------
__device__ __nv_bfloat16 g_xh[(size_t)NROW * DD];   // bf16 hi of x
__device__ __nv_bfloat16 g_xl[(size_t)NROW * DD];   // bf16 lo of x
__device__ __nv_bfloat16 g_mh[(size_t)NROW * DD];   // bf16 hi of mixed
__device__ __nv_bfloat16 g_ml[(size_t)NROW * DD];   // bf16 lo of mixed
__device__ __nv_bfloat16 g_wh1[DD * DD], g_wl1[DD * DD];  // W_proj hi/lo
__device__ __nv_bfloat16 g_wh2[DD * DD], g_wl2[DD * DD];  // out_W hi/lo
__device__ float g_heads[(size_t)NROW * DD];        // heads fp32, later y
__device__ float g_part[BB * 128 * DD];             // partial sums
__device__ float g_summary[BB * DD];                // per-batch column sums
__device__ float g_coef[BB * HH * HH];              // 0.1/(1+imp), zero diag

__device__ __forceinline__ uint32_t smem_to_u32(const void* smem_ptr) {
    uint32_t addr;
    asm("{ .reg .u64 tmp; cvta.to.shared.u64 tmp, %1; cvt.u32.u64 %0, tmp; }"
        : "=r"(addr) : "l"(smem_ptr));
    return addr;
}

__device__ __forceinline__ void cpasync16(uint32_t dst, const void* src) {
    asm volatile("cp.async.cg.shared.global [%0], [%1], 16;"
                 :: "r"(dst), "l"(src) : "memory");
}

#define CP_COMMIT() asm volatile("cp.async.commit_group;" ::: "memory")
#define CP_WAIT2()  asm volatile("cp.async.wait_group 2;" ::: "memory")

#define LDSM4(r, addr) \
    asm volatile("ldmatrix.sync.aligned.m8n8.x4.shared.b16 {%0,%1,%2,%3}, [%4];" \
        : "=r"((r)[0]), "=r"((r)[1]), "=r"((r)[2]), "=r"((r)[3]) : "r"(addr))

__device__ __forceinline__ void mma_bf16(float* c, const uint32_t* a,
                                         uint32_t b0, uint32_t b1) {
    asm volatile(
        "mma.sync.aligned.m16n8k16.row.col.f32.bf16.bf16.f32 "
        "{%0,%1,%2,%3}, {%4,%5,%6,%7}, {%8,%9}, {%0,%1,%2,%3};"
        : "+f"(c[0]), "+f"(c[1]), "+f"(c[2]), "+f"(c[3])
        : "r"(a[0]), "r"(a[1]), "r"(a[2]), "r"(a[3]), "r"(b0), "r"(b1));
}

// ---------------------------------------------------------------------------
// bf16 hi/lo split conversion.  WHICH: 0 = x, 1 = W_proj, 2 = out_W
// ---------------------------------------------------------------------------
template<int WHICH>
__global__ void convert_split(const float* __restrict__ src, int n4)
{
    int i = blockIdx.x * blockDim.x + threadIdx.x;
    if (i >= n4) return;
    __nv_bfloat16* hp = (WHICH == 0) ? g_xh : ((WHICH == 1) ? g_wh1 : g_wh2);
    __nv_bfloat16* lp = (WHICH == 0) ? g_xl : ((WHICH == 1) ? g_wl1 : g_wl2);
    float4 v = ((const float4*)src)[i];
    __nv_bfloat162 h01 = __floats2bfloat162_rn(v.x, v.y);
    __nv_bfloat162 h23 = __floats2bfloat162_rn(v.z, v.w);
    __nv_bfloat162 l01 = __floats2bfloat162_rn(v.x - __low2float(h01),
                                               v.y - __high2float(h01));
    __nv_bfloat162 l23 = __floats2bfloat162_rn(v.z - __low2float(h23),
                                               v.w - __high2float(h23));
    ((__nv_bfloat162*)hp)[2 * i + 0] = h01;
    ((__nv_bfloat162*)hp)[2 * i + 1] = h23;
    ((__nv_bfloat162*)lp)[2 * i + 0] = l01;
    ((__nv_bfloat162*)lp)[2 * i + 1] = l23;
}

// ---------------------------------------------------------------------------
// mma.sync GEMM: C[n,m] = sum_d A[n,d]*W[m,d] via 3xbf16 split.
// 128x128 tile, BK=32, 256 threads (8 warps, warp tile 64x32), 3-stage cp.async.
//   MODE 0: A = x(hi/lo),     epilogue: * cos(freq[m]*pi)      -> g_heads
//   MODE 1: A = mixed(hi/lo), epilogue: + out_b[m] + x[n,m]    -> g_heads
// SMEM rows padded to 80B -> conflict-free ldmatrix phases.
// ---------------------------------------------------------------------------
#define RSB   80                 // row stride bytes (32 bf16 + 16B pad)
#define OPB   (128 * RSB)        // 10240 bytes per operand tile
#define STGB  (4 * OPB)          // 40960 bytes per stage (Ah|Al|Bh|Bl)
#define NSTG  3
#define GEMM_SMEM (NSTG * STGB)  // 122880

template<int MODE>
__global__ __launch_bounds__(256, 1)
void gemm_mma(const float* __restrict__ xres, const float* __restrict__ aux)
{
    extern __shared__ char sm[];
    const uint32_t sb = smem_to_u32(sm);
    const int tid = threadIdx.x;
    const int lane = tid & 31;
    const int wid = tid >> 5;
    const int wm = wid & 1;          // 2 M groups of 64
    const int wn = wid >> 1;         // 4 N groups of 32
    const int bc = blockIdx.x;       // col tile 0..7
    const int br = blockIdx.y;       // row tile 0..127

    const __nv_bfloat16* Ah = (MODE == 0) ? g_xh : g_mh;
    const __nv_bfloat16* Al = (MODE == 0) ? g_xl : g_ml;
    const __nv_bfloat16* Bh = (MODE == 0) ? g_wh1 : g_wh2;
    const __nv_bfloat16* Bl = (MODE == 0) ? g_wl1 : g_wl2;

    // ---- loader mapping: 8 x 16B per thread per stage ----
    const char* gp[8];
    uint32_t    sp[8];
#pragma unroll
    for (int t = 0; t < 8; t++) {
        int idx = tid + t * 256;          // 0..2047
        int op  = idx >> 9;               // 0..3 : Ah,Al,Bh,Bl
        int rem = idx & 511;
        int row = rem >> 2;               // 0..127
        int seg = rem & 3;                // 16B segment within 64B row chunk
        const __nv_bfloat16* base = (op == 0) ? Ah : (op == 1) ? Al : (op == 2) ? Bh : Bl;
        int tilebase = ((op < 2) ? br : bc) * 128;
        gp[t] = (const char*)(base + (size_t)(tilebase + row) * DD + seg * 8);
        sp[t] = sb + op * OPB + row * RSB + seg * 16;
    }

    // ---- ldmatrix source addresses (within a stage) ----
    // A: lanes 0-15 -> rows m0..15 @ col 0; lanes 16-31 -> rows @ col 8 (=16B)
    const uint32_t aoff = (uint32_t)((wm * 64 + (lane & 15)) * RSB + (lane >> 4) * 16);
    // B: rows n = wn*32 + ((lane>>4)<<3) + (lane&7); col byte = ((lane>>3)&1)*16
    const uint32_t boff = (uint32_t)((wn * 32 + ((lane >> 4) << 3) + (lane & 7)) * RSB
                                     + ((lane >> 3) & 1) * 16);

    float acc[4][4][4];
#pragma unroll
    for (int i = 0; i < 4; i++)
#pragma unroll
        for (int j = 0; j < 4; j++)
#pragma unroll
            for (int q = 0; q < 4; q++) acc[i][j][q] = 0.f;

    // ---- prologue: fill 3 stages ----
#pragma unroll
    for (int s = 0; s < NSTG; s++) {
#pragma unroll
        for (int t = 0; t < 8; t++)
            cpasync16(sp[t] + s * STGB, gp[t] + s * 64);
        CP_COMMIT();
    }

    // ---- main loop over 32 k-chunks ----
    for (int c = 0; c < 32; c++) {
        CP_WAIT2();
        __syncthreads();
        const uint32_t stg = sb + (c % NSTG) * STGB;
        const uint32_t sAh = stg + aoff;
        const uint32_t sAl = stg + OPB + aoff;
        const uint32_t sBh = stg + 2 * OPB + boff;
        const uint32_t sBl = stg + 3 * OPB + boff;

#pragma unroll
        for (int kk = 0; kk < 2; kk++) {          // two k16 steps (32B each)
            uint32_t ah[4][4], al[4][4];
#pragma unroll
            for (int mi = 0; mi < 4; mi++) {
                LDSM4(ah[mi], sAh + mi * (16 * RSB) + kk * 32);
                LDSM4(al[mi], sAl + mi * (16 * RSB) + kk * 32);
            }
            uint32_t bh[2][4], bl[2][4];
#pragma unroll
            for (int g = 0; g < 2; g++) {
                LDSM4(bh[g], sBh + g * (16 * RSB) + kk * 32);
                LDSM4(bl[g], sBl + g * (16 * RSB) + kk * 32);
            }
#pragma unroll
            for (int mi = 0; mi < 4; mi++)
#pragma unroll
                for (int ni = 0; ni < 4; ni++) {
                    const int g = ni >> 1, i0 = (ni & 1) * 2;
                    mma_bf16(acc[mi][ni], ah[mi], bh[g][i0], bh[g][i0 + 1]);
                    mma_bf16(acc[mi][ni], ah[mi], bl[g][i0], bl[g][i0 + 1]);
                    mma_bf16(acc[mi][ni], al[mi], bh[g][i0], bh[g][i0 + 1]);
                }
        }
        __syncthreads();
        if (c + NSTG < 32) {
#pragma unroll
            for (int t = 0; t < 8; t++)
                cpasync16(sp[t] + ((c + NSTG) % NSTG) * STGB, gp[t] + (c + NSTG) * 64);
        }
        CP_COMMIT();
    }

    // ---- epilogue: fused scale / bias+residual, direct stores ----
    const int mbase = br * 128 + wm * 64;
    const int nbase = bc * 128 + wn * 32;
    const int rq = lane >> 2;
    const int cq = (lane & 3) * 2;
#pragma unroll
    for (int ni = 0; ni < 4; ni++) {
        const int col = nbase + ni * 8 + cq;
        float f0, f1;
        if (MODE == 0) {
            f0 = cosf(aux[col] * PI_F);
            f1 = cosf(aux[col + 1] * PI_F);
        } else {
            f0 = aux[col];
            f1 = aux[col + 1];
        }
#pragma unroll
        for (int mi = 0; mi < 4; mi++) {
            const int r0 = mbase + mi * 16 + rq;
            float* p0 = g_heads + (size_t)r0 * DD + col;
            float* p1 = g_heads + (size_t)(r0 + 8) * DD + col;
            float2 o0, o1;
            if (MODE == 0) {
                o0.x = acc[mi][ni][0] * f0; o0.y = acc[mi][ni][1] * f1;
                o1.x = acc[mi][ni][2] * f0; o1.y = acc[mi][ni][3] * f1;
            } else {
                float2 x0 = *(const float2*)(xres + (size_t)r0 * DD + col);
                float2 x1 = *(const float2*)(xres + (size_t)(r0 + 8) * DD + col);
                o0.x = acc[mi][ni][0] + f0 + x0.x; o0.y = acc[mi][ni][1] + f1 + x0.y;
                o1.x = acc[mi][ni][2] + f0 + x1.x; o1.y = acc[mi][ni][3] + f1 + x1.y;
            }
            *(float2*)p0 = o0;
            *(float2*)p1 = o1;
        }
    }
}

// ---------------------------------------------------------------------------
// Summary reduction (deterministic, two stages)
// ---------------------------------------------------------------------------
__global__ void reduce_stage1()
{
    const int schunk = blockIdx.x;   // 0..127 (chunks of 32 s)
    const int b = blockIdx.y;
    const int t = threadIdx.x;       // 0..255
    float acc[4] = {0.f, 0.f, 0.f, 0.f};
    const float* base = g_heads + ((size_t)b * SS + (size_t)schunk * 32) * DD;
    for (int s = 0; s < 32; s++) {
#pragma unroll
        for (int q = 0; q < 4; q++)
            acc[q] += base[(size_t)s * DD + q * 256 + t];
    }
    float* out = g_part + (size_t)(b * 128 + schunk) * DD;
#pragma unroll
    for (int q = 0; q < 4; q++) out[q * 256 + t] = acc[q];
}

__global__ void reduce_stage2()
{
    const int idx = blockIdx.x * 256 + threadIdx.x;  // 0..4095
    const int b = idx >> 10;
    const int d = idx & 1023;
    float s = 0.f;
#pragma unroll 8
    for (int c = 0; c < 128; c++)
        s += g_part[(size_t)(b * 128 + c) * DD + d];
    g_summary[idx] = s;
}

// ---------------------------------------------------------------------------
// Polarity / impedance / coef (one block per batch, 256 threads)
// ---------------------------------------------------------------------------
__global__ void polarity_kernel(const float* __restrict__ pol_W,
                                const float* __restrict__ pol_b,
                                const float* __restrict__ W1,
                                const float* __restrict__ b1,
                                const float* __restrict__ W2,
                                const float* __restrict__ b2,
                                float* __restrict__ imp_out)
{
    const int b = blockIdx.x;
    const int w = threadIdx.x >> 5;      // head
    const int lane = threadIdx.x & 31;   // polarity index
    __shared__ float s_sum[DD];
    __shared__ float s_pol[HH][PP];

    for (int i = threadIdx.x; i < DD; i += 256)
        s_sum[i] = g_summary[b * DD + i] * (1.0f / (float)SS);
    __syncthreads();

    float acc = pol_b[w * PP + lane];
    const float* pw = pol_W + (size_t)(w * PP + lane) * KK;
#pragma unroll 8
    for (int k = 0; k < KK; k++)
        acc += s_sum[w * KK + k] * pw[k];
    float p = tanhf(acc);

    float ss = p * p;
#pragma unroll
    for (int o = 16; o; o >>= 1) ss += __shfl_xor_sync(0xffffffffu, ss, o);
    p = p / fmaxf(sqrtf(ss), 1e-12f);
    s_pol[w][lane] = p;
    __syncthreads();

    if (threadIdx.x < HH * HH) {
        const int i = threadIdx.x >> 3;
        const int j = threadIdx.x & 7;
        float d = 0.f;
#pragma unroll
        for (int pp = 0; pp < PP; pp++) d += s_pol[i][pp] * s_pol[j][pp];

        float sum2 = b2[0];
#pragma unroll
        for (int c = 0; c < 16; c++) {
            float z = d * W1[c] + b1[c];
            float g = 0.5f * z * (1.f + erff(z * 0.70710678118654752f));
            sum2 += g * W2[c];
        }
        float imp = (sum2 > 0.f) ? sum2 + log1pf(expf(-sum2)) : log1pf(expf(sum2));
        if (i == j) imp = 0.f;
        imp_out[b * 64 + threadIdx.x] = imp;
        g_coef[b * 64 + threadIdx.x] = (i == j) ? 0.f : 0.1f / (1.f + imp);
    }
}

// ---------------------------------------------------------------------------
// Cross-head mixing with causal scale -> bf16 hi/lo (GEMM2 A operand)
// ---------------------------------------------------------------------------
__global__ void mixing_kernel(const int* __restrict__ causal)
{
    const int bs = blockIdx.x;          // 0..16383
    const int b = bs >> 12;
    const int s = bs & (SS - 1);
    const int k = threadIdx.x;          // 0..127
    __shared__ float sc[HH * HH];
    if (threadIdx.x < HH * HH) sc[threadIdx.x] = g_coef[b * 64 + threadIdx.x];
    __syncthreads();

    const float* row = g_heads + (size_t)bs * DD;
    float v[HH];
#pragma unroll
    for (int j = 0; j < HH; j++) v[j] = row[j * KK + k];

    const float scale = (*causal) ? (float)(s + 1) * (1.0f / (float)SS) : 1.0f;

    __nv_bfloat16* oh = g_mh + (size_t)bs * DD;
    __nv_bfloat16* ol = g_ml + (size_t)bs * DD;
#pragma unroll
    for (int i = 0; i < HH; i++) {
        float t = 0.f;
#pragma unroll
        for (int j = 0; j < HH; j++) t += sc[i * 8 + j] * v[j];
        float val = v[i] + scale * t;
        __nv_bfloat16 h = __float2bfloat16(val);
        oh[i * KK + k] = h;
        ol[i * KK + k] = __float2bfloat16(val - __bfloat162float(h));
    }
}

// ---------------------------------------------------------------------------
// LayerNorm over D (y lives in g_heads after GEMM2)
// ---------------------------------------------------------------------------
__global__ void layernorm_kernel(const float* __restrict__ gamma,
                                 const float* __restrict__ beta,
                                 float* __restrict__ out)
{
    const int row = blockIdx.x;
    const int t = threadIdx.x;          // 0..255
    const float4 v = ((const float4*)(g_heads + (size_t)row * DD))[t];
    float s  = v.x + v.y + v.z + v.w;
    float s2 = v.x * v.x + v.y * v.y + v.z * v.z + v.w * v.w;

#pragma unroll
    for (int o = 16; o; o >>= 1) {
        s  += __shfl_xor_sync(0xffffffffu, s, o);
        s2 += __shfl_xor_sync(0xffffffffu, s2, o);
    }
    __shared__ float sh[8], sh2[8];
    const int w = t >> 5, lane = t & 31;
    if (lane == 0) { sh[w] = s; sh2[w] = s2; }
    __syncthreads();
    if (w == 0) {
        s  = (lane < 8) ? sh[lane]  : 0.f;
        s2 = (lane < 8) ? sh2[lane] : 0.f;
#pragma unroll
        for (int o = 4; o; o >>= 1) {
            s  += __shfl_xor_sync(0xffffffffu, s, o);
            s2 += __shfl_xor_sync(0xffffffffu, s2, o);
        }
        if (lane == 0) { sh[0] = s; sh2[0] = s2; }
    }
    __syncthreads();
    const float mu  = sh[0] * (1.f / (float)DD);
    const float var = sh2[0] * (1.f / (float)DD) - mu * mu;
    const float inv = rsqrtf(var + 1e-5f);

    const float4 g4 = ((const float4*)gamma)[t];
    const float4 b4 = ((const float4*)beta)[t];
    float4 o4;
    o4.x = (v.x - mu) * inv * g4.x + b4.x;
    o4.y = (v.y - mu) * inv * g4.y + b4.y;
    o4.z = (v.z - mu) * inv * g4.z + b4.z;
    o4.w = (v.w - mu) * inv * g4.w + b4.w;
    ((float4*)(out + (size_t)row * DD))[t] = o4;
}

// ---------------------------------------------------------------------------
extern "C" void kernel_launch(void* const* d_in, const int* in_sizes, int n_in,
                              void* d_out, int out_size)
{
    const float* x      = (const float*)d_in[0];   // (B,S,D)
    const float* W_proj = (const float*)d_in[1];   // (H,K,D) -> (1024,1024)
    const float* freqs  = (const float*)d_in[2];   // (H,K) -> 1024
    const float* pol_W  = (const float*)d_in[3];
    const float* pol_b  = (const float*)d_in[4];
    const float* imp_W1 = (const float*)d_in[5];
    const float* imp_b1 = (const float*)d_in[6];
    const float* imp_W2 = (const float*)d_in[7];
    const float* imp_b2 = (const float*)d_in[8];
    const float* out_W  = (const float*)d_in[9];
    const float* out_b  = (const float*)d_in[10];
    const float* ln_g   = (const float*)d_in[11];
    const float* ln_b   = (const float*)d_in[12];
    const int*   causal = (const int*)d_in[13];

    float* out = (float*)d_out;
    float* imp_out = out + (out_size - BB * HH * HH);  // impedance tail

    cudaFuncSetAttribute(gemm_mma<0>, cudaFuncAttributeMaxDynamicSharedMemorySize, GEMM_SMEM);
    cudaFuncSetAttribute(gemm_mma<1>, cudaFuncAttributeMaxDynamicSharedMemorySize, GEMM_SMEM);

    dim3 ggrid(DD / 128, NROW / 128);  // (8, 128): col fastest for A reuse in L2

    // 0) bf16 hi/lo splits of x, W_proj, out_W
    convert_split<0><<<(NROW * DD / 4 + 255) / 256, 256>>>(x, NROW * DD / 4);
    convert_split<1><<<(DD * DD / 4 + 255) / 256, 256>>>(W_proj, DD * DD / 4);
    convert_split<2><<<(DD * DD / 4 + 255) / 256, 256>>>(out_W, DD * DD / 4);
    // 1) heads = (x @ W_proj^T) * cos(freq*pi)   -> g_heads   [mma.sync 3xbf16]
    gemm_mma<0><<<ggrid, 256, GEMM_SMEM>>>(x, freqs);
    // 2) summary column sums (deterministic two-stage)
    reduce_stage1<<<dim3(128, BB), 256>>>();
    reduce_stage2<<<16, 256>>>();
    // 3) pol / impedance / coef (writes impedance to output tail)
    polarity_kernel<<<BB, 256>>>(pol_W, pol_b, imp_W1, imp_b1, imp_W2, imp_b2, imp_out);
    // 4) cross-head mixing with causal scale     -> g_mh/g_ml (bf16 split)
    mixing_kernel<<<NROW, 128>>>(causal);
    // 5) y = mixed @ out_W^T + out_b + x         -> g_heads   [mma.sync 3xbf16]
    gemm_mma<1><<<ggrid, 256, GEMM_SMEM>>>(x, out_b);
    // 6) LayerNorm -> d_out
    layernorm_kernel<<<NROW, 256>>>(ln_g, ln_b, out);
}

// round 8
// speedup vs baseline: 4.6028x; 1.1436x over previous
#include <cuda_runtime.h>
#include <cuda_bf16.h>
#include <math.h>
#include <stdint.h>

// Problem constants
#define BB 4
#define SS 4096
#define DD 1024
#define HH 8
#define KK 128
#define PP 32
#define NROW (BB*SS)          // 16384
#define PI_F 3.14159265358979f

// ---------------------------------------------------------------------------
// Device-global scratch (no allocations allowed)
// ---------------------------------------------------------------------------
__device__ __nv_bfloat16 g_xh[(size_t)NROW * DD];   // bf16 hi of x
__device__ __nv_bfloat16 g_xl[(size_t)NROW * DD];   // bf16 lo of x
__device__ __nv_bfloat16 g_mh[(size_t)NROW * DD];   // bf16 hi of mixed
__device__ __nv_bfloat16 g_ml[(size_t)NROW * DD];   // bf16 lo of mixed
__device__ __nv_bfloat16 g_wh1[DD * DD], g_wl1[DD * DD];  // W_proj hi/lo
__device__ __nv_bfloat16 g_wh2[DD * DD], g_wl2[DD * DD];  // out_W hi/lo
__device__ float g_heads[(size_t)NROW * DD];        // heads fp32, later y
__device__ float g_part[BB * 128 * DD];             // partial sums
__device__ float g_summary[BB * DD];                // per-batch column sums
__device__ float g_coef[BB * HH * HH];              // 0.1/(1+imp), zero diag

__device__ __forceinline__ uint32_t smem_to_u32(const void* smem_ptr) {
    uint32_t addr;
    asm("{ .reg .u64 tmp; cvta.to.shared.u64 tmp, %1; cvt.u32.u64 %0, tmp; }"
        : "=r"(addr) : "l"(smem_ptr));
    return addr;
}

__device__ __forceinline__ void cpasync16(uint32_t dst, const void* src) {
    asm volatile("cp.async.cg.shared.global [%0], [%1], 16;"
                 :: "r"(dst), "l"(src) : "memory");
}

#define CP_COMMIT() asm volatile("cp.async.commit_group;" ::: "memory")
#define CP_WAIT1()  asm volatile("cp.async.wait_group 1;" ::: "memory")

#define LDSM4(r, addr) \
    asm volatile("ldmatrix.sync.aligned.m8n8.x4.shared.b16 {%0,%1,%2,%3}, [%4];" \
        : "=r"((r)[0]), "=r"((r)[1]), "=r"((r)[2]), "=r"((r)[3]) : "r"(addr))

__device__ __forceinline__ void mma_bf16(float* c, const uint32_t* a,
                                         uint32_t b0, uint32_t b1) {
    asm volatile(
        "mma.sync.aligned.m16n8k16.row.col.f32.bf16.bf16.f32 "
        "{%0,%1,%2,%3}, {%4,%5,%6,%7}, {%8,%9}, {%0,%1,%2,%3};"
        : "+f"(c[0]), "+f"(c[1]), "+f"(c[2]), "+f"(c[3])
        : "r"(a[0]), "r"(a[1]), "r"(a[2]), "r"(a[3]), "r"(b0), "r"(b1));
}

// ---------------------------------------------------------------------------
// bf16 hi/lo split conversion.  WHICH: 0 = x, 1 = W_proj, 2 = out_W
// ---------------------------------------------------------------------------
template<int WHICH>
__global__ void convert_split(const float* __restrict__ src, int n4)
{
    int i = blockIdx.x * blockDim.x + threadIdx.x;
    if (i >= n4) return;
    __nv_bfloat16* hp = (WHICH == 0) ? g_xh : ((WHICH == 1) ? g_wh1 : g_wh2);
    __nv_bfloat16* lp = (WHICH == 0) ? g_xl : ((WHICH == 1) ? g_wl1 : g_wl2);
    float4 v = ((const float4*)src)[i];
    __nv_bfloat162 h01 = __floats2bfloat162_rn(v.x, v.y);
    __nv_bfloat162 h23 = __floats2bfloat162_rn(v.z, v.w);
    __nv_bfloat162 l01 = __floats2bfloat162_rn(v.x - __low2float(h01),
                                               v.y - __high2float(h01));
    __nv_bfloat162 l23 = __floats2bfloat162_rn(v.z - __low2float(h23),
                                               v.w - __high2float(h23));
    ((__nv_bfloat162*)hp)[2 * i + 0] = h01;
    ((__nv_bfloat162*)hp)[2 * i + 1] = h23;
    ((__nv_bfloat162*)lp)[2 * i + 0] = l01;
    ((__nv_bfloat162*)lp)[2 * i + 1] = l23;
}

// ---------------------------------------------------------------------------
// mma.sync GEMM: C[n,m] = sum_d A[n,d]*W[m,d] via 3xbf16 split.
// 128x128 tile, BK=32, 128 threads (4 warps, warp tile 64x64), 2-stage
// cp.async pipeline, 2 CTAs/SM.
//   MODE 0: A = x(hi/lo),     epilogue: * cos(freq[m]*pi)      -> g_heads
//   MODE 1: A = mixed(hi/lo), epilogue: + out_b[m] + x[n,m]    -> g_heads
// SMEM rows padded to 80B -> conflict-free ldmatrix phases.
// ---------------------------------------------------------------------------
#define RSB   80                 // row stride bytes (32 bf16 + 16B pad)
#define OPB   (128 * RSB)        // 10240 bytes per operand tile
#define STGB  (4 * OPB)          // 40960 bytes per stage (Ah|Al|Bh|Bl)
#define NSTG  2
#define GEMM_SMEM (NSTG * STGB)  // 81920

template<int MODE>
__global__ __launch_bounds__(128, 2)
void gemm_mma(const float* __restrict__ xres, const float* __restrict__ aux)
{
    extern __shared__ char sm[];
    const uint32_t sb = smem_to_u32(sm);
    const int tid = threadIdx.x;
    const int lane = tid & 31;
    const int wid = tid >> 5;        // 0..3
    const int wm = wid & 1;          // 2 M groups of 64
    const int wn = wid >> 1;         // 2 N groups of 64
    const int bc = blockIdx.x;       // col tile 0..7
    const int br = blockIdx.y;       // row tile 0..127

    const __nv_bfloat16* Ah = (MODE == 0) ? g_xh : g_mh;
    const __nv_bfloat16* Al = (MODE == 0) ? g_xl : g_ml;
    const __nv_bfloat16* Bh = (MODE == 0) ? g_wh1 : g_wh2;
    const __nv_bfloat16* Bl = (MODE == 0) ? g_wl1 : g_wl2;

    // ---- loader mapping: 16 x 16B per thread per stage ----
    // thread covers row (h*32 + tid>>2), segment (tid&3) of each operand
    const int r4  = tid >> 2;       // 0..31
    const int seg = tid & 3;        // 16B segment (64B of payload per row)
    const __nv_bfloat16* gbase[4];
    gbase[0] = Ah + (size_t)(br * 128 + r4) * DD + seg * 8;
    gbase[1] = Al + (size_t)(br * 128 + r4) * DD + seg * 8;
    gbase[2] = Bh + (size_t)(bc * 128 + r4) * DD + seg * 8;
    gbase[3] = Bl + (size_t)(bc * 128 + r4) * DD + seg * 8;
    const uint32_t sload = sb + r4 * RSB + seg * 16;

    // ---- ldmatrix source offsets (within a stage) ----
    const uint32_t aoff = (uint32_t)((wm * 64 + (lane & 15)) * RSB + (lane >> 4) * 16);
    const uint32_t boff = (uint32_t)((wn * 64 + ((lane >> 4) << 3) + (lane & 7)) * RSB
                                     + ((lane >> 3) & 1) * 16);

    float acc[4][8][4];
#pragma unroll
    for (int i = 0; i < 4; i++)
#pragma unroll
        for (int j = 0; j < 8; j++)
#pragma unroll
            for (int q = 0; q < 4; q++) acc[i][j][q] = 0.f;

    // ---- prologue: fill 2 stages ----
#pragma unroll
    for (int s = 0; s < NSTG; s++) {
#pragma unroll
        for (int op = 0; op < 4; op++)
#pragma unroll
            for (int h = 0; h < 4; h++)
                cpasync16(sload + s * STGB + op * OPB + h * (32 * RSB),
                          gbase[op] + (size_t)h * 32 * DD + s * 32);
        CP_COMMIT();
    }

    // ---- main loop over 32 k-chunks ----
    for (int c = 0; c < 32; c++) {
        CP_WAIT1();
        __syncthreads();
        const uint32_t stg = sb + (c & 1) * STGB;

#pragma unroll
        for (int kk = 0; kk < 2; kk++) {
            uint32_t ah[4][4], al[4][4];
#pragma unroll
            for (int mi = 0; mi < 4; mi++) {
                LDSM4(ah[mi], stg + aoff + mi * (16 * RSB) + kk * 32);
                LDSM4(al[mi], stg + OPB + aoff + mi * (16 * RSB) + kk * 32);
            }
#pragma unroll
            for (int g = 0; g < 4; g++) {
                uint32_t bh[4], bl[4];
                LDSM4(bh, stg + 2 * OPB + boff + g * (16 * RSB) + kk * 32);
                LDSM4(bl, stg + 3 * OPB + boff + g * (16 * RSB) + kk * 32);
#pragma unroll
                for (int mi = 0; mi < 4; mi++)
#pragma unroll
                    for (int nl = 0; nl < 2; nl++) {
                        const int i0 = nl * 2;
                        float* a = acc[mi][g * 2 + nl];
                        mma_bf16(a, ah[mi], bh[i0], bh[i0 + 1]);
                        mma_bf16(a, ah[mi], bl[i0], bl[i0 + 1]);
                        mma_bf16(a, al[mi], bh[i0], bh[i0 + 1]);
                    }
            }
        }
        __syncthreads();
        if (c + NSTG < 32) {
            const uint32_t dst = sload + (c & 1) * STGB;
#pragma unroll
            for (int op = 0; op < 4; op++)
#pragma unroll
                for (int h = 0; h < 4; h++)
                    cpasync16(dst + op * OPB + h * (32 * RSB),
                              gbase[op] + (size_t)h * 32 * DD + (c + NSTG) * 32);
        }
        CP_COMMIT();
    }

    // ---- epilogue: fused scale / bias+residual, direct stores ----
    const int mbase = br * 128 + wm * 64;
    const int nbase = bc * 128 + wn * 64;
    const int rq = lane >> 2;
    const int cq = (lane & 3) * 2;
#pragma unroll
    for (int ni = 0; ni < 8; ni++) {
        const int col = nbase + ni * 8 + cq;
        float f0, f1;
        if (MODE == 0) {
            f0 = cosf(aux[col] * PI_F);
            f1 = cosf(aux[col + 1] * PI_F);
        } else {
            f0 = aux[col];
            f1 = aux[col + 1];
        }
#pragma unroll
        for (int mi = 0; mi < 4; mi++) {
            const int r0 = mbase + mi * 16 + rq;
            float* p0 = g_heads + (size_t)r0 * DD + col;
            float* p1 = g_heads + (size_t)(r0 + 8) * DD + col;
            float2 o0, o1;
            if (MODE == 0) {
                o0.x = acc[mi][ni][0] * f0; o0.y = acc[mi][ni][1] * f1;
                o1.x = acc[mi][ni][2] * f0; o1.y = acc[mi][ni][3] * f1;
            } else {
                float2 x0 = *(const float2*)(xres + (size_t)r0 * DD + col);
                float2 x1 = *(const float2*)(xres + (size_t)(r0 + 8) * DD + col);
                o0.x = acc[mi][ni][0] + f0 + x0.x; o0.y = acc[mi][ni][1] + f1 + x0.y;
                o1.x = acc[mi][ni][2] + f0 + x1.x; o1.y = acc[mi][ni][3] + f1 + x1.y;
            }
            *(float2*)p0 = o0;
            *(float2*)p1 = o1;
        }
    }
}

// ---------------------------------------------------------------------------
// Summary reduction (deterministic, two stages)
// ---------------------------------------------------------------------------
__global__ void reduce_stage1()
{
    const int schunk = blockIdx.x;   // 0..127 (chunks of 32 s)
    const int b = blockIdx.y;
    const int t = threadIdx.x;       // 0..255
    float acc[4] = {0.f, 0.f, 0.f, 0.f};
    const float* base = g_heads + ((size_t)b * SS + (size_t)schunk * 32) * DD;
    for (int s = 0; s < 32; s++) {
#pragma unroll
        for (int q = 0; q < 4; q++)
            acc[q] += base[(size_t)s * DD + q * 256 + t];
    }
    float* out = g_part + (size_t)(b * 128 + schunk) * DD;
#pragma unroll
    for (int q = 0; q < 4; q++) out[q * 256 + t] = acc[q];
}

__global__ void reduce_stage2()
{
    const int idx = blockIdx.x * 256 + threadIdx.x;  // 0..4095
    const int b = idx >> 10;
    const int d = idx & 1023;
    float s = 0.f;
#pragma unroll 8
    for (int c = 0; c < 128; c++)
        s += g_part[(size_t)(b * 128 + c) * DD + d];
    g_summary[idx] = s;
}

// ---------------------------------------------------------------------------
// Polarity / impedance / coef (one block per batch, 256 threads)
// ---------------------------------------------------------------------------
__global__ void polarity_kernel(const float* __restrict__ pol_W,
                                const float* __restrict__ pol_b,
                                const float* __restrict__ W1,
                                const float* __restrict__ b1,
                                const float* __restrict__ W2,
                                const float* __restrict__ b2,
                                float* __restrict__ imp_out)
{
    const int b = blockIdx.x;
    const int w = threadIdx.x >> 5;      // head
    const int lane = threadIdx.x & 31;   // polarity index
    __shared__ float s_sum[DD];
    __shared__ float s_pol[HH][PP];

    for (int i = threadIdx.x; i < DD; i += 256)
        s_sum[i] = g_summary[b * DD + i] * (1.0f / (float)SS);
    __syncthreads();

    float acc = pol_b[w * PP + lane];
    const float* pw = pol_W + (size_t)(w * PP + lane) * KK;
#pragma unroll 8
    for (int k = 0; k < KK; k++)
        acc += s_sum[w * KK + k] * pw[k];
    float p = tanhf(acc);

    float ss = p * p;
#pragma unroll
    for (int o = 16; o; o >>= 1) ss += __shfl_xor_sync(0xffffffffu, ss, o);
    p = p / fmaxf(sqrtf(ss), 1e-12f);
    s_pol[w][lane] = p;
    __syncthreads();

    if (threadIdx.x < HH * HH) {
        const int i = threadIdx.x >> 3;
        const int j = threadIdx.x & 7;
        float d = 0.f;
#pragma unroll
        for (int pp = 0; pp < PP; pp++) d += s_pol[i][pp] * s_pol[j][pp];

        float sum2 = b2[0];
#pragma unroll
        for (int c = 0; c < 16; c++) {
            float z = d * W1[c] + b1[c];
            float g = 0.5f * z * (1.f + erff(z * 0.70710678118654752f));
            sum2 += g * W2[c];
        }
        float imp = (sum2 > 0.f) ? sum2 + log1pf(expf(-sum2)) : log1pf(expf(sum2));
        if (i == j) imp = 0.f;
        imp_out[b * 64 + threadIdx.x] = imp;
        g_coef[b * 64 + threadIdx.x] = (i == j) ? 0.f : 0.1f / (1.f + imp);
    }
}

// ---------------------------------------------------------------------------
// Cross-head mixing with causal scale -> bf16 hi/lo (GEMM2 A operand)
// ---------------------------------------------------------------------------
__global__ void mixing_kernel(const int* __restrict__ causal)
{
    const int bs = blockIdx.x;          // 0..16383
    const int b = bs >> 12;
    const int s = bs & (SS - 1);
    const int k = threadIdx.x;          // 0..127
    __shared__ float sc[HH * HH];
    if (threadIdx.x < HH * HH) sc[threadIdx.x] = g_coef[b * 64 + threadIdx.x];
    __syncthreads();

    const float* row = g_heads + (size_t)bs * DD;
    float v[HH];
#pragma unroll
    for (int j = 0; j < HH; j++) v[j] = row[j * KK + k];

    const float scale = (*causal) ? (float)(s + 1) * (1.0f / (float)SS) : 1.0f;

    __nv_bfloat16* oh = g_mh + (size_t)bs * DD;
    __nv_bfloat16* ol = g_ml + (size_t)bs * DD;
#pragma unroll
    for (int i = 0; i < HH; i++) {
        float t = 0.f;
#pragma unroll
        for (int j = 0; j < HH; j++) t += sc[i * 8 + j] * v[j];
        float val = v[i] + scale * t;
        __nv_bfloat16 h = __float2bfloat16(val);
        oh[i * KK + k] = h;
        ol[i * KK + k] = __float2bfloat16(val - __bfloat162float(h));
    }
}

// ---------------------------------------------------------------------------
// LayerNorm over D (y lives in g_heads after GEMM2)
// ---------------------------------------------------------------------------
__global__ void layernorm_kernel(const float* __restrict__ gamma,
                                 const float* __restrict__ beta,
                                 float* __restrict__ out)
{
    const int row = blockIdx.x;
    const int t = threadIdx.x;          // 0..255
    const float4 v = ((const float4*)(g_heads + (size_t)row * DD))[t];
    float s  = v.x + v.y + v.z + v.w;
    float s2 = v.x * v.x + v.y * v.y + v.z * v.z + v.w * v.w;

#pragma unroll
    for (int o = 16; o; o >>= 1) {
        s  += __shfl_xor_sync(0xffffffffu, s, o);
        s2 += __shfl_xor_sync(0xffffffffu, s2, o);
    }
    __shared__ float sh[8], sh2[8];
    const int w = t >> 5, lane = t & 31;
    if (lane == 0) { sh[w] = s; sh2[w] = s2; }
    __syncthreads();
    if (w == 0) {
        s  = (lane < 8) ? sh[lane]  : 0.f;
        s2 = (lane < 8) ? sh2[lane] : 0.f;
#pragma unroll
        for (int o = 4; o; o >>= 1) {
            s  += __shfl_xor_sync(0xffffffffu, s, o);
            s2 += __shfl_xor_sync(0xffffffffu, s2, o);
        }
        if (lane == 0) { sh[0] = s; sh2[0] = s2; }
    }
    __syncthreads();
    const float mu  = sh[0] * (1.f / (float)DD);
    const float var = sh2[0] * (1.f / (float)DD) - mu * mu;
    const float inv = rsqrtf(var + 1e-5f);

    const float4 g4 = ((const float4*)gamma)[t];
    const float4 b4 = ((const float4*)beta)[t];
    float4 o4;
    o4.x = (v.x - mu) * inv * g4.x + b4.x;
    o4.y = (v.y - mu) * inv * g4.y + b4.y;
    o4.z = (v.z - mu) * inv * g4.z + b4.z;
    o4.w = (v.w - mu) * inv * g4.w + b4.w;
    ((float4*)(out + (size_t)row * DD))[t] = o4;
}

// ---------------------------------------------------------------------------
extern "C" void kernel_launch(void* const* d_in, const int* in_sizes, int n_in,
                              void* d_out, int out_size)
{
    const float* x      = (const float*)d_in[0];   // (B,S,D)
    const float* W_proj = (const float*)d_in[1];   // (H,K,D) -> (1024,1024)
    const float* freqs  = (const float*)d_in[2];   // (H,K) -> 1024
    const float* pol_W  = (const float*)d_in[3];
    const float* pol_b  = (const float*)d_in[4];
    const float* imp_W1 = (const float*)d_in[5];
    const float* imp_b1 = (const float*)d_in[6];
    const float* imp_W2 = (const float*)d_in[7];
    const float* imp_b2 = (const float*)d_in[8];
    const float* out_W  = (const float*)d_in[9];
    const float* out_b  = (const float*)d_in[10];
    const float* ln_g   = (const float*)d_in[11];
    const float* ln_b   = (const float*)d_in[12];
    const int*   causal = (const int*)d_in[13];

    float* out = (float*)d_out;
    float* imp_out = out + (out_size - BB * HH * HH);  // impedance tail

    cudaFuncSetAttribute(gemm_mma<0>, cudaFuncAttributeMaxDynamicSharedMemorySize, GEMM_SMEM);
    cudaFuncSetAttribute(gemm_mma<1>, cudaFuncAttributeMaxDynamicSharedMemorySize, GEMM_SMEM);

    dim3 ggrid(DD / 128, NROW / 128);  // (8, 128): col fastest for A reuse in L2

    // 0) bf16 hi/lo splits of x, W_proj, out_W
    convert_split<0><<<(NROW * DD / 4 + 255) / 256, 256>>>(x, NROW * DD / 4);
    convert_split<1><<<(DD * DD / 4 + 255) / 256, 256>>>(W_proj, DD * DD / 4);
    convert_split<2><<<(DD * DD / 4 + 255) / 256, 256>>>(out_W, DD * DD / 4);
    // 1) heads = (x @ W_proj^T) * cos(freq*pi)   -> g_heads   [mma.sync 3xbf16]
    gemm_mma<0><<<ggrid, 128, GEMM_SMEM>>>(x, freqs);
    // 2) summary column sums (deterministic two-stage)
    reduce_stage1<<<dim3(128, BB), 256>>>();
    reduce_stage2<<<16, 256>>>();
    // 3) pol / impedance / coef (writes impedance to output tail)
    polarity_kernel<<<BB, 256>>>(pol_W, pol_b, imp_W1, imp_b1, imp_W2, imp_b2, imp_out);
    // 4) cross-head mixing with causal scale     -> g_mh/g_ml (bf16 split)
    mixing_kernel<<<NROW, 128>>>(causal);
    // 5) y = mixed @ out_W^T + out_b + x         -> g_heads   [mma.sync 3xbf16]
    gemm_mma<1><<<ggrid, 128, GEMM_SMEM>>>(x, out_b);
    // 6) LayerNorm -> d_out
    layernorm_kernel<<<NROW, 256>>>(ln_g, ln_b, out);
}